// round 1
// baseline (speedup 1.0000x reference)
#include <cuda_runtime.h>
#include <cstdint>
#include <math.h>

#define S_LEN   2048
#define DHEAD   128
#define NHEADS  64        // B*H = 4*16
#define BM      128
#define BN      64
#define THREADS 256
#define KSTRIDE 136       // row stride (floats) for Q/K/V smem: 136 % 32 == 8 -> conflict-free frags
#define PSTRIDE 72        // row stride for P smem: 72 % 32 == 8

// (1/0.32) * log2(e)
#define SFACT   4.5084219932497354f

static __device__ __forceinline__ uint32_t f32_to_tf32(float x) {
    uint32_t r;
    asm("cvt.rna.tf32.f32 %0, %1;" : "=r"(r) : "f"(x));
    return r;
}

static __device__ __forceinline__ float ex2f(float x) {
    float r;
    asm("ex2.approx.f32 %0, %1;" : "=f"(r) : "f"(x));
    return r;
}

static __device__ __forceinline__ void mma_tf32(float* d, const uint32_t* a, const uint32_t* b) {
    asm volatile(
        "mma.sync.aligned.m16n8k8.row.col.f32.tf32.tf32.f32 "
        "{%0,%1,%2,%3}, {%4,%5,%6,%7}, {%8,%9}, {%0,%1,%2,%3};\n"
        : "+f"(d[0]), "+f"(d[1]), "+f"(d[2]), "+f"(d[3])
        : "r"(a[0]), "r"(a[1]), "r"(a[2]), "r"(a[3]), "r"(b[0]), "r"(b[1]));
}

__global__ __launch_bounds__(THREADS, 1)
void fa_tf32_kernel(const float* __restrict__ Q, const float* __restrict__ K,
                    const float* __restrict__ V, float* __restrict__ O) {
    extern __shared__ float smem[];
    float* Qs = smem;                         // BM * KSTRIDE
    float* Ks = Qs + BM * KSTRIDE;            // BN * KSTRIDE
    float* Vs = Ks + BN * KSTRIDE;            // BN * KSTRIDE
    float* Ps = Vs + BN * KSTRIDE;            // BM * PSTRIDE

    const int tid  = threadIdx.x;
    const int warp = tid >> 5;
    const int lane = tid & 31;
    const int g    = lane >> 2;   // group id (row within 8-row half)
    const int c    = lane & 3;    // thread-in-group

    const int bh = blockIdx.y;
    const int q0 = blockIdx.x * BM;
    const size_t head = (size_t)bh * S_LEN * DHEAD;

    // ---- load Q tile (coalesced float4) into smem ----
    for (int i = tid; i < BM * DHEAD / 4; i += THREADS) {
        int row = i >> 5;               // DHEAD/4 = 32 float4 per row
        int col = (i & 31) << 2;
        float4 v4 = *(const float4*)(Q + head + (size_t)(q0 + row) * DHEAD + col);
        *(float4*)(Qs + row * KSTRIDE + col) = v4;
    }

    const int rbase = warp * 16;
    float o[16][4];
    #pragma unroll
    for (int i = 0; i < 16; i++) { o[i][0] = 0.f; o[i][1] = 0.f; o[i][2] = 0.f; o[i][3] = 0.f; }
    float m0 = -INFINITY, m1 = -INFINITY, l0 = 0.f, l1 = 0.f;

    for (int jt = 0; jt < S_LEN / BN; ++jt) {
        __syncthreads();   // prior tile's smem reads complete (also covers Q-load at jt=0)
        const int k0 = jt * BN;
        for (int i = tid; i < BN * DHEAD / 4; i += THREADS) {
            int row = i >> 5;
            int col = (i & 31) << 2;
            size_t gidx = head + (size_t)(k0 + row) * DHEAD + col;
            *(float4*)(Ks + row * KSTRIDE + col) = *(const float4*)(K + gidx);
            *(float4*)(Vs + row * KSTRIDE + col) = *(const float4*)(V + gidx);
        }
        __syncthreads();

        // ---- S = Q K^T via 3xTF32 (hi/lo split of both operands) ----
        float s[8][4];
        #pragma unroll
        for (int i = 0; i < 8; i++) { s[i][0] = 0.f; s[i][1] = 0.f; s[i][2] = 0.f; s[i][3] = 0.f; }

        #pragma unroll 4
        for (int kk = 0; kk < 16; ++kk) {
            // A frag: rows rbase+g, rbase+g+8 ; cols kk*8+c, +4
            float a0 = Qs[(rbase + g)     * KSTRIDE + kk * 8 + c];
            float a1 = Qs[(rbase + g + 8) * KSTRIDE + kk * 8 + c];
            float a2 = Qs[(rbase + g)     * KSTRIDE + kk * 8 + c + 4];
            float a3 = Qs[(rbase + g + 8) * KSTRIDE + kk * 8 + c + 4];
            uint32_t ah[4], al[4];
            ah[0] = f32_to_tf32(a0); al[0] = f32_to_tf32(a0 - __uint_as_float(ah[0]));
            ah[1] = f32_to_tf32(a1); al[1] = f32_to_tf32(a1 - __uint_as_float(ah[1]));
            ah[2] = f32_to_tf32(a2); al[2] = f32_to_tf32(a2 - __uint_as_float(ah[2]));
            ah[3] = f32_to_tf32(a3); al[3] = f32_to_tf32(a3 - __uint_as_float(ah[3]));
            #pragma unroll
            for (int ng = 0; ng < 8; ++ng) {
                // B frag: k-dim = kk*8 + c (+4), key = ng*8 + g
                float b0f = Ks[(ng * 8 + g) * KSTRIDE + kk * 8 + c];
                float b1f = Ks[(ng * 8 + g) * KSTRIDE + kk * 8 + c + 4];
                uint32_t bh2[2], bl2[2];
                bh2[0] = f32_to_tf32(b0f); bl2[0] = f32_to_tf32(b0f - __uint_as_float(bh2[0]));
                bh2[1] = f32_to_tf32(b1f); bl2[1] = f32_to_tf32(b1f - __uint_as_float(bh2[1]));
                mma_tf32(s[ng], ah, bh2);
                mma_tf32(s[ng], al, bh2);
                mma_tf32(s[ng], ah, bl2);
            }
        }

        // ---- online softmax (base-2 domain, scale folded in) ----
        float mx0 = -INFINITY, mx1 = -INFINITY;
        #pragma unroll
        for (int ng = 0; ng < 8; ++ng) {
            s[ng][0] *= SFACT; s[ng][1] *= SFACT; s[ng][2] *= SFACT; s[ng][3] *= SFACT;
            mx0 = fmaxf(mx0, fmaxf(s[ng][0], s[ng][1]));
            mx1 = fmaxf(mx1, fmaxf(s[ng][2], s[ng][3]));
        }
        mx0 = fmaxf(mx0, __shfl_xor_sync(0xffffffffu, mx0, 1));
        mx0 = fmaxf(mx0, __shfl_xor_sync(0xffffffffu, mx0, 2));
        mx1 = fmaxf(mx1, __shfl_xor_sync(0xffffffffu, mx1, 1));
        mx1 = fmaxf(mx1, __shfl_xor_sync(0xffffffffu, mx1, 2));

        float m0n = fmaxf(m0, mx0), m1n = fmaxf(m1, mx1);
        float al0 = ex2f(m0 - m0n), al1 = ex2f(m1 - m1n);
        float sum0 = 0.f, sum1 = 0.f;
        #pragma unroll
        for (int ng = 0; ng < 8; ++ng) {
            s[ng][0] = ex2f(s[ng][0] - m0n);
            s[ng][1] = ex2f(s[ng][1] - m0n);
            s[ng][2] = ex2f(s[ng][2] - m1n);
            s[ng][3] = ex2f(s[ng][3] - m1n);
            sum0 += s[ng][0] + s[ng][1];
            sum1 += s[ng][2] + s[ng][3];
        }
        sum0 += __shfl_xor_sync(0xffffffffu, sum0, 1);
        sum0 += __shfl_xor_sync(0xffffffffu, sum0, 2);
        sum1 += __shfl_xor_sync(0xffffffffu, sum1, 1);
        sum1 += __shfl_xor_sync(0xffffffffu, sum1, 2);
        l0 = l0 * al0 + sum0;
        l1 = l1 * al1 + sum1;
        m0 = m0n; m1 = m1n;
        #pragma unroll
        for (int nf = 0; nf < 16; ++nf) {
            o[nf][0] *= al0; o[nf][1] *= al0; o[nf][2] *= al1; o[nf][3] *= al1;
        }

        // ---- stage P (accum layout -> A-frag layout) through warp-private smem ----
        float* pw = Ps + rbase * PSTRIDE;
        __syncwarp();
        #pragma unroll
        for (int ng = 0; ng < 8; ++ng) {
            *(float2*)(pw + (g)     * PSTRIDE + ng * 8 + c * 2) = make_float2(s[ng][0], s[ng][1]);
            *(float2*)(pw + (g + 8) * PSTRIDE + ng * 8 + c * 2) = make_float2(s[ng][2], s[ng][3]);
        }
        __syncwarp();

        // ---- O += P V (plain tf32) ----
        #pragma unroll 2
        for (int k2 = 0; k2 < 8; ++k2) {
            uint32_t pa[4];
            pa[0] = f32_to_tf32(pw[(g)     * PSTRIDE + k2 * 8 + c]);
            pa[1] = f32_to_tf32(pw[(g + 8) * PSTRIDE + k2 * 8 + c]);
            pa[2] = f32_to_tf32(pw[(g)     * PSTRIDE + k2 * 8 + c + 4]);
            pa[3] = f32_to_tf32(pw[(g + 8) * PSTRIDE + k2 * 8 + c + 4]);
            #pragma unroll
            for (int nf = 0; nf < 16; ++nf) {
                uint32_t vb[2];
                // B frag: key = k2*8 + c (+4), dim = nf*8 + g
                vb[0] = f32_to_tf32(Vs[(k2 * 8 + c)     * KSTRIDE + nf * 8 + g]);
                vb[1] = f32_to_tf32(Vs[(k2 * 8 + c + 4) * KSTRIDE + nf * 8 + g]);
                mma_tf32(o[nf], pa, vb);
            }
        }
    }

    // ---- epilogue: normalize and store ----
    float inv0 = 1.f / l0, inv1 = 1.f / l1;
    size_t obase = head + (size_t)(q0 + rbase) * DHEAD;
    #pragma unroll
    for (int nf = 0; nf < 16; ++nf) {
        *(float2*)(O + obase + (size_t)(g)     * DHEAD + nf * 8 + c * 2) =
            make_float2(o[nf][0] * inv0, o[nf][1] * inv0);
        *(float2*)(O + obase + (size_t)(g + 8) * DHEAD + nf * 8 + c * 2) =
            make_float2(o[nf][2] * inv1, o[nf][3] * inv1);
    }
}

extern "C" void kernel_launch(void* const* d_in, const int* in_sizes, int n_in,
                              void* d_out, int out_size) {
    const float* q = (const float*)d_in[0];
    const float* k = (const float*)d_in[1];
    const float* v = (const float*)d_in[2];
    float* o = (float*)d_out;

    const size_t smem_bytes =
        (size_t)(BM * KSTRIDE + 2 * BN * KSTRIDE + BM * PSTRIDE) * sizeof(float); // 176128 B

    cudaFuncSetAttribute(fa_tf32_kernel, cudaFuncAttributeMaxDynamicSharedMemorySize,
                         (int)smem_bytes);

    dim3 grid(S_LEN / BM, NHEADS);
    fa_tf32_kernel<<<grid, THREADS, smem_bytes>>>(q, k, v, o);
}

// round 2
// speedup vs baseline: 1.0995x; 1.0995x over previous
#include <cuda_runtime.h>
#include <cstdint>
#include <math.h>

#define S_LEN   2048
#define DHEAD   128
#define NHEADS  64        // B*H = 4*16
#define BM      128
#define BN      64
#define THREADS 256
#define KSTRIDE 136       // fp32/tf32 row stride (words): 136 % 32 == 8 -> conflict-free frags
#define KHL     264       // K hi/lo interleaved row stride (words): 264 % 32 == 8
#define PSTRIDE 72        // P row stride (words): 72 % 32 == 8

// (1/0.32) * log2(e), folded into Q at load
#define SFACT   4.5084219932497354f

static __device__ __forceinline__ uint32_t f32_to_tf32(float x) {
    uint32_t r;
    asm("cvt.rna.tf32.f32 %0, %1;" : "=r"(r) : "f"(x));
    return r;
}

static __device__ __forceinline__ float ex2f(float x) {
    float r;
    asm("ex2.approx.f32 %0, %1;" : "=f"(r) : "f"(x));
    return r;
}

static __device__ __forceinline__ void mma_tf32(float* d, const uint32_t* a, const uint32_t* b) {
    asm volatile(
        "mma.sync.aligned.m16n8k8.row.col.f32.tf32.tf32.f32 "
        "{%0,%1,%2,%3}, {%4,%5,%6,%7}, {%8,%9}, {%0,%1,%2,%3};\n"
        : "+f"(d[0]), "+f"(d[1]), "+f"(d[2]), "+f"(d[3])
        : "r"(a[0]), "r"(a[1]), "r"(a[2]), "r"(a[3]), "r"(b[0]), "r"(b[1]));
}

__global__ __launch_bounds__(THREADS, 1)
void fa_tf32_kernel(const float* __restrict__ Q, const float* __restrict__ K,
                    const float* __restrict__ V, float* __restrict__ O) {
    extern __shared__ float smem[];
    float*    Qs  = smem;                                   // BM * KSTRIDE fp32 (pre-scaled)
    uint32_t* Khl = (uint32_t*)(smem + BM * KSTRIDE);       // BN * KHL  (hi,lo interleaved)
    uint32_t* Vt  = Khl + BN * KHL;                         // BN * KSTRIDE (tf32)
    uint32_t* Ps  = Vt + BN * KSTRIDE;                      // BM * PSTRIDE (tf32)

    const int tid  = threadIdx.x;
    const int warp = tid >> 5;
    const int lane = tid & 31;
    const int g    = lane >> 2;   // group id (row within 8-row half)
    const int c    = lane & 3;    // thread-in-group

    const int bh = blockIdx.y;
    const int q0 = blockIdx.x * BM;
    const size_t head = (size_t)bh * S_LEN * DHEAD;

    // ---- load Q tile, fold in softmax scale ----
    for (int i = tid; i < BM * DHEAD / 4; i += THREADS) {
        int row = i >> 5;               // DHEAD/4 = 32 float4 per row
        int col = (i & 31) << 2;
        float4 v4 = *(const float4*)(Q + head + (size_t)(q0 + row) * DHEAD + col);
        v4.x *= SFACT; v4.y *= SFACT; v4.z *= SFACT; v4.w *= SFACT;
        *(float4*)(Qs + row * KSTRIDE + col) = v4;
    }

    const int rbase = warp * 16;
    float o[16][4];
    #pragma unroll
    for (int i = 0; i < 16; i++) { o[i][0] = 0.f; o[i][1] = 0.f; o[i][2] = 0.f; o[i][3] = 0.f; }
    float m0 = -INFINITY, m1 = -INFINITY, l0 = 0.f, l1 = 0.f;

    for (int jt = 0; jt < S_LEN / BN; ++jt) {
        __syncthreads();   // prior tile's smem reads complete (also covers Q-load at jt=0)
        const int k0 = jt * BN;
        for (int i = tid; i < BN * DHEAD / 4; i += THREADS) {
            int row = i >> 5;
            int col = (i & 31) << 2;
            size_t gidx = head + (size_t)(k0 + row) * DHEAD + col;
            float4 kv = *(const float4*)(K + gidx);
            float4 vv = *(const float4*)(V + gidx);
            // K -> hi/lo tf32, interleaved
            uint32_t h0 = f32_to_tf32(kv.x), h1 = f32_to_tf32(kv.y);
            uint32_t h2 = f32_to_tf32(kv.z), h3 = f32_to_tf32(kv.w);
            uint32_t l0k = f32_to_tf32(kv.x - __uint_as_float(h0));
            uint32_t l1k = f32_to_tf32(kv.y - __uint_as_float(h1));
            uint32_t l2k = f32_to_tf32(kv.z - __uint_as_float(h2));
            uint32_t l3k = f32_to_tf32(kv.w - __uint_as_float(h3));
            uint32_t* kdst = Khl + row * KHL + col * 2;
            *(uint4*)(kdst)     = make_uint4(h0, l0k, h1, l1k);
            *(uint4*)(kdst + 4) = make_uint4(h2, l2k, h3, l3k);
            // V -> tf32
            *(uint4*)(Vt + row * KSTRIDE + col) =
                make_uint4(f32_to_tf32(vv.x), f32_to_tf32(vv.y),
                           f32_to_tf32(vv.z), f32_to_tf32(vv.w));
        }
        __syncthreads();

        // ---- S = Q K^T via 3xTF32 (hi/lo split of both operands) ----
        float s[8][4];
        #pragma unroll
        for (int i = 0; i < 8; i++) { s[i][0] = 0.f; s[i][1] = 0.f; s[i][2] = 0.f; s[i][3] = 0.f; }

        #pragma unroll 2
        for (int kk = 0; kk < 16; ++kk) {
            // A frag: rows rbase+g, rbase+g+8 ; cols kk*8+c, +4 (split per kk: cheap)
            float a0 = Qs[(rbase + g)     * KSTRIDE + kk * 8 + c];
            float a1 = Qs[(rbase + g + 8) * KSTRIDE + kk * 8 + c];
            float a2 = Qs[(rbase + g)     * KSTRIDE + kk * 8 + c + 4];
            float a3 = Qs[(rbase + g + 8) * KSTRIDE + kk * 8 + c + 4];
            uint32_t ah[4], al[4];
            ah[0] = f32_to_tf32(a0); al[0] = f32_to_tf32(a0 - __uint_as_float(ah[0]));
            ah[1] = f32_to_tf32(a1); al[1] = f32_to_tf32(a1 - __uint_as_float(ah[1]));
            ah[2] = f32_to_tf32(a2); al[2] = f32_to_tf32(a2 - __uint_as_float(ah[2]));
            ah[3] = f32_to_tf32(a3); al[3] = f32_to_tf32(a3 - __uint_as_float(ah[3]));

            // preload all B fragments (hi+lo) for this kk
            uint32_t bh2[8][2], bl2[8][2];
            #pragma unroll
            for (int ng = 0; ng < 8; ++ng) {
                const uint32_t* kb = Khl + (ng * 8 + g) * KHL + (kk * 8 + c) * 2;
                uint2 t0 = *(const uint2*)(kb);
                uint2 t1 = *(const uint2*)(kb + 8);  // col + 4 -> +8 words
                bh2[ng][0] = t0.x; bl2[ng][0] = t0.y;
                bh2[ng][1] = t1.x; bl2[ng][1] = t1.y;
            }
            // grouped by term: 8 independent accumulators per burst
            #pragma unroll
            for (int ng = 0; ng < 8; ++ng) mma_tf32(s[ng], ah, bh2[ng]);
            #pragma unroll
            for (int ng = 0; ng < 8; ++ng) mma_tf32(s[ng], al, bh2[ng]);
            #pragma unroll
            for (int ng = 0; ng < 8; ++ng) mma_tf32(s[ng], ah, bl2[ng]);
        }

        // ---- online softmax (base-2 domain; scale already folded into Q) ----
        float mx0 = -INFINITY, mx1 = -INFINITY;
        #pragma unroll
        for (int ng = 0; ng < 8; ++ng) {
            mx0 = fmaxf(mx0, fmaxf(s[ng][0], s[ng][1]));
            mx1 = fmaxf(mx1, fmaxf(s[ng][2], s[ng][3]));
        }
        mx0 = fmaxf(mx0, __shfl_xor_sync(0xffffffffu, mx0, 1));
        mx0 = fmaxf(mx0, __shfl_xor_sync(0xffffffffu, mx0, 2));
        mx1 = fmaxf(mx1, __shfl_xor_sync(0xffffffffu, mx1, 1));
        mx1 = fmaxf(mx1, __shfl_xor_sync(0xffffffffu, mx1, 2));

        float m0n = fmaxf(m0, mx0), m1n = fmaxf(m1, mx1);
        float al0 = ex2f(m0 - m0n), al1 = ex2f(m1 - m1n);
        float sum0 = 0.f, sum1 = 0.f;
        #pragma unroll
        for (int ng = 0; ng < 8; ++ng) {
            s[ng][0] = ex2f(s[ng][0] - m0n);
            s[ng][1] = ex2f(s[ng][1] - m0n);
            s[ng][2] = ex2f(s[ng][2] - m1n);
            s[ng][3] = ex2f(s[ng][3] - m1n);
            sum0 += s[ng][0] + s[ng][1];
            sum1 += s[ng][2] + s[ng][3];
        }
        sum0 += __shfl_xor_sync(0xffffffffu, sum0, 1);
        sum0 += __shfl_xor_sync(0xffffffffu, sum0, 2);
        sum1 += __shfl_xor_sync(0xffffffffu, sum1, 1);
        sum1 += __shfl_xor_sync(0xffffffffu, sum1, 2);
        l0 = l0 * al0 + sum0;
        l1 = l1 * al1 + sum1;
        m0 = m0n; m1 = m1n;
        #pragma unroll
        for (int nf = 0; nf < 16; ++nf) {
            o[nf][0] *= al0; o[nf][1] *= al0; o[nf][2] *= al1; o[nf][3] *= al1;
        }

        // ---- stage P as tf32 (accum layout -> A-frag layout) via warp-private smem ----
        uint32_t* pw = Ps + rbase * PSTRIDE;
        __syncwarp();
        #pragma unroll
        for (int ng = 0; ng < 8; ++ng) {
            *(uint2*)(pw + (g)     * PSTRIDE + ng * 8 + c * 2) =
                make_uint2(f32_to_tf32(s[ng][0]), f32_to_tf32(s[ng][1]));
            *(uint2*)(pw + (g + 8) * PSTRIDE + ng * 8 + c * 2) =
                make_uint2(f32_to_tf32(s[ng][2]), f32_to_tf32(s[ng][3]));
        }
        __syncwarp();

        // ---- O += P V (plain tf32, operands pre-converted) ----
        #pragma unroll 2
        for (int k2 = 0; k2 < 8; ++k2) {
            uint32_t pa[4];
            pa[0] = pw[(g)     * PSTRIDE + k2 * 8 + c];
            pa[1] = pw[(g + 8) * PSTRIDE + k2 * 8 + c];
            pa[2] = pw[(g)     * PSTRIDE + k2 * 8 + c + 4];
            pa[3] = pw[(g + 8) * PSTRIDE + k2 * 8 + c + 4];
            #pragma unroll
            for (int nf = 0; nf < 16; ++nf) {
                uint32_t vb[2];
                vb[0] = Vt[(k2 * 8 + c)     * KSTRIDE + nf * 8 + g];
                vb[1] = Vt[(k2 * 8 + c + 4) * KSTRIDE + nf * 8 + g];
                mma_tf32(o[nf], pa, vb);
            }
        }
    }

    // ---- epilogue: normalize and store ----
    float inv0 = 1.f / l0, inv1 = 1.f / l1;
    size_t obase = head + (size_t)(q0 + rbase) * DHEAD;
    #pragma unroll
    for (int nf = 0; nf < 16; ++nf) {
        *(float2*)(O + obase + (size_t)(g)     * DHEAD + nf * 8 + c * 2) =
            make_float2(o[nf][0] * inv0, o[nf][1] * inv0);
        *(float2*)(O + obase + (size_t)(g + 8) * DHEAD + nf * 8 + c * 2) =
            make_float2(o[nf][2] * inv1, o[nf][3] * inv1);
    }
}

extern "C" void kernel_launch(void* const* d_in, const int* in_sizes, int n_in,
                              void* d_out, int out_size) {
    const float* q = (const float*)d_in[0];
    const float* k = (const float*)d_in[1];
    const float* v = (const float*)d_in[2];
    float* o = (float*)d_out;

    const size_t smem_bytes =
        (size_t)(BM * KSTRIDE + BN * KHL + BN * KSTRIDE + BM * PSTRIDE) * sizeof(float); // 208896 B

    cudaFuncSetAttribute(fa_tf32_kernel, cudaFuncAttributeMaxDynamicSharedMemorySize,
                         (int)smem_bytes);

    dim3 grid(S_LEN / BM, NHEADS);
    fa_tf32_kernel<<<grid, THREADS, smem_bytes>>>(q, k, v, o);
}

// round 3
// speedup vs baseline: 1.8314x; 1.6656x over previous
#include <cuda_runtime.h>
#include <cuda_fp16.h>
#include <cstdint>
#include <math.h>

#define S_LEN   2048
#define DHEAD   128
#define NHEADS  64        // B*H = 4*16
#define BM      128
#define BN      64
#define THREADS 256
#define SSTR    136       // fp16 row stride: 272B -> 68 words == 4 mod 32, ldmatrix conflict-free
#define ROWB    272       // SSTR * 2 bytes

// (1/0.32) * log2(e), folded into Q at load
#define SFACT   4.5084219932497354f

static __device__ __forceinline__ float ex2f(float x) {
    float r;
    asm("ex2.approx.f32 %0, %1;" : "=f"(r) : "f"(x));
    return r;
}

static __device__ __forceinline__ uint32_t pack_h2(float a, float b) {
    __half2 h = __floats2half2_rn(a, b);   // x = a (lo), y = b (hi)
    return *reinterpret_cast<uint32_t*>(&h);
}

static __device__ __forceinline__ void ldsm4(uint32_t* r, uint32_t a) {
    asm volatile("ldmatrix.sync.aligned.m8n8.x4.shared.b16 {%0,%1,%2,%3}, [%4];"
                 : "=r"(r[0]), "=r"(r[1]), "=r"(r[2]), "=r"(r[3]) : "r"(a));
}

static __device__ __forceinline__ void ldsm4t(uint32_t* r, uint32_t a) {
    asm volatile("ldmatrix.sync.aligned.m8n8.x4.trans.shared.b16 {%0,%1,%2,%3}, [%4];"
                 : "=r"(r[0]), "=r"(r[1]), "=r"(r[2]), "=r"(r[3]) : "r"(a));
}

static __device__ __forceinline__ void mma_f16(float* d, const uint32_t* a, const uint32_t* b) {
    asm volatile(
        "mma.sync.aligned.m16n8k16.row.col.f32.f16.f16.f32 "
        "{%0,%1,%2,%3}, {%4,%5,%6,%7}, {%8,%9}, {%0,%1,%2,%3};\n"
        : "+f"(d[0]), "+f"(d[1]), "+f"(d[2]), "+f"(d[3])
        : "r"(a[0]), "r"(a[1]), "r"(a[2]), "r"(a[3]), "r"(b[0]), "r"(b[1]));
}

// split 8 consecutive floats into hi/lo fp16 planes (packed half2 x4)
static __device__ __forceinline__ void split8(const float* x, uint4& uh, uint4& ul) {
    uint32_t h[4], l[4];
    #pragma unroll
    for (int j = 0; j < 4; ++j) {
        float a = x[2 * j], b = x[2 * j + 1];
        __half ha = __float2half_rn(a), hb = __float2half_rn(b);
        float ra = a - __half2float(ha);
        float rb = b - __half2float(hb);
        h[j] = pack_h2(__half2float(ha), __half2float(hb));
        l[j] = pack_h2(ra, rb);
    }
    uh = make_uint4(h[0], h[1], h[2], h[3]);
    ul = make_uint4(l[0], l[1], l[2], l[3]);
}

static __device__ __forceinline__ uint4 pack8(const float* x) {
    return make_uint4(pack_h2(x[0], x[1]), pack_h2(x[2], x[3]),
                      pack_h2(x[4], x[5]), pack_h2(x[6], x[7]));
}

__global__ __launch_bounds__(THREADS, 1)
void fa_f16_kernel(const float* __restrict__ Q, const float* __restrict__ K,
                   const float* __restrict__ V, float* __restrict__ O) {
    extern __shared__ __align__(16) char smraw[];
    __half* Qh = (__half*)smraw;              // BM * SSTR
    __half* Ql = Qh + BM * SSTR;              // BM * SSTR
    __half* Kh = Ql + BM * SSTR;              // BN * SSTR
    __half* Kl = Kh + BN * SSTR;              // BN * SSTR
    __half* Vh = Kl + BN * SSTR;              // BN * SSTR

    const int tid  = threadIdx.x;
    const int warp = tid >> 5;
    const int lane = tid & 31;
    const int g    = lane >> 2;
    const int c    = lane & 3;

    const int bh = blockIdx.y;
    const int q0 = blockIdx.x * BM;
    const size_t head = (size_t)bh * S_LEN * DHEAD;
    const int rbase = warp * 16;

    // ---- load Q tile: scale, split hi/lo fp16 ----
    for (int i = tid; i < BM * 16; i += THREADS) {
        int row = i >> 4, ch = i & 15;
        const float* src = Q + head + (size_t)(q0 + row) * DHEAD + ch * 8;
        float f[8];
        float4 f0 = *(const float4*)src;
        float4 f1 = *(const float4*)(src + 4);
        f[0] = f0.x * SFACT; f[1] = f0.y * SFACT; f[2] = f0.z * SFACT; f[3] = f0.w * SFACT;
        f[4] = f1.x * SFACT; f[5] = f1.y * SFACT; f[6] = f1.z * SFACT; f[7] = f1.w * SFACT;
        uint4 uh, ul;
        split8(f, uh, ul);
        *(uint4*)(Qh + row * SSTR + ch * 8) = uh;
        *(uint4*)(Ql + row * SSTR + ch * 8) = ul;
    }

    // ---- fragment smem addresses (bytes) ----
    const uint32_t qh_base = (uint32_t)__cvta_generic_to_shared(Qh);
    const uint32_t ql_base = (uint32_t)__cvta_generic_to_shared(Ql);
    const uint32_t kh_base = (uint32_t)__cvta_generic_to_shared(Kh);
    const uint32_t kl_base = (uint32_t)__cvta_generic_to_shared(Kl);
    const uint32_t vh_base = (uint32_t)__cvta_generic_to_shared(Vh);

    // A (Q): rows rbase + (lane&15); k-chunk (lane>>4)
    const uint32_t aoff = (uint32_t)(rbase + (lane & 15)) * ROWB + (lane >> 4) * 16;
    const uint32_t qh_a = qh_base + aoff;
    const uint32_t ql_a = ql_base + aoff;
    // B (K): rows (lane&7) + 8*(lane>>4) [+16*ngp]; k-chunk ((lane>>3)&1)
    const uint32_t boff = (uint32_t)((lane & 7) + ((lane >> 4) << 3)) * ROWB + ((lane >> 3) & 1) * 16;
    const uint32_t kh_b = kh_base + boff;
    const uint32_t kl_b = kl_base + boff;
    // B (V, trans): rows (lane&7) + 8*((lane>>3)&1) [+16*k2]; d-chunk (lane>>4) [+2*nfp]
    const uint32_t voff = (uint32_t)((lane & 7) + (((lane >> 3) & 1) << 3)) * ROWB + (lane >> 4) * 16;
    const uint32_t vh_b = vh_base + voff;

    float o[16][4];
    #pragma unroll
    for (int i = 0; i < 16; i++) { o[i][0] = 0.f; o[i][1] = 0.f; o[i][2] = 0.f; o[i][3] = 0.f; }
    float m0 = -INFINITY, m1 = -INFINITY, l0 = 0.f, l1 = 0.f;

    for (int jt = 0; jt < S_LEN / BN; ++jt) {
        __syncthreads();   // previous tile's smem reads complete (covers Q load at jt=0)
        const int k0 = jt * BN;
        for (int i = tid; i < BN * 16; i += THREADS) {
            int row = i >> 4, ch = i & 15;
            size_t gidx = head + (size_t)(k0 + row) * DHEAD + ch * 8;
            float kf[8], vf[8];
            float4 t0 = *(const float4*)(K + gidx);
            float4 t1 = *(const float4*)(K + gidx + 4);
            kf[0]=t0.x; kf[1]=t0.y; kf[2]=t0.z; kf[3]=t0.w;
            kf[4]=t1.x; kf[5]=t1.y; kf[6]=t1.z; kf[7]=t1.w;
            float4 u0 = *(const float4*)(V + gidx);
            float4 u1 = *(const float4*)(V + gidx + 4);
            vf[0]=u0.x; vf[1]=u0.y; vf[2]=u0.z; vf[3]=u0.w;
            vf[4]=u1.x; vf[5]=u1.y; vf[6]=u1.z; vf[7]=u1.w;
            uint4 uh, ul;
            split8(kf, uh, ul);
            *(uint4*)(Kh + row * SSTR + ch * 8) = uh;
            *(uint4*)(Kl + row * SSTR + ch * 8) = ul;
            *(uint4*)(Vh + row * SSTR + ch * 8) = pack8(vf);
        }
        __syncthreads();

        // ---- S = Q K^T : 3x fp16 split (hh, lh, hl) ----
        float s[8][4];
        #pragma unroll
        for (int i = 0; i < 8; i++) { s[i][0]=0.f; s[i][1]=0.f; s[i][2]=0.f; s[i][3]=0.f; }

        #pragma unroll 2
        for (int kk = 0; kk < 8; ++kk) {
            uint32_t aH[4], aL[4];
            ldsm4(aH, qh_a + kk * 32);
            ldsm4(aL, ql_a + kk * 32);
            uint32_t bhf[16], blf[16];
            #pragma unroll
            for (int ngp = 0; ngp < 4; ++ngp) {
                ldsm4(&bhf[ngp * 4], kh_b + (uint32_t)ngp * (16 * ROWB) + kk * 32);
                ldsm4(&blf[ngp * 4], kl_b + (uint32_t)ngp * (16 * ROWB) + kk * 32);
            }
            #pragma unroll
            for (int ng = 0; ng < 8; ++ng) mma_f16(s[ng], aH, &bhf[ng * 2]);
            #pragma unroll
            for (int ng = 0; ng < 8; ++ng) mma_f16(s[ng], aL, &bhf[ng * 2]);
            #pragma unroll
            for (int ng = 0; ng < 8; ++ng) mma_f16(s[ng], aH, &blf[ng * 2]);
        }

        // ---- online softmax (base-2 domain; scale folded into Q) ----
        float mx0 = -INFINITY, mx1 = -INFINITY;
        #pragma unroll
        for (int ng = 0; ng < 8; ++ng) {
            mx0 = fmaxf(mx0, fmaxf(s[ng][0], s[ng][1]));
            mx1 = fmaxf(mx1, fmaxf(s[ng][2], s[ng][3]));
        }
        mx0 = fmaxf(mx0, __shfl_xor_sync(0xffffffffu, mx0, 1));
        mx0 = fmaxf(mx0, __shfl_xor_sync(0xffffffffu, mx0, 2));
        mx1 = fmaxf(mx1, __shfl_xor_sync(0xffffffffu, mx1, 1));
        mx1 = fmaxf(mx1, __shfl_xor_sync(0xffffffffu, mx1, 2));

        float m0n = fmaxf(m0, mx0), m1n = fmaxf(m1, mx1);
        float al0 = ex2f(m0 - m0n), al1 = ex2f(m1 - m1n);
        float sum0 = 0.f, sum1 = 0.f;
        #pragma unroll
        for (int ng = 0; ng < 8; ++ng) {
            s[ng][0] = ex2f(s[ng][0] - m0n);
            s[ng][1] = ex2f(s[ng][1] - m0n);
            s[ng][2] = ex2f(s[ng][2] - m1n);
            s[ng][3] = ex2f(s[ng][3] - m1n);
            sum0 += s[ng][0] + s[ng][1];
            sum1 += s[ng][2] + s[ng][3];
        }
        sum0 += __shfl_xor_sync(0xffffffffu, sum0, 1);
        sum0 += __shfl_xor_sync(0xffffffffu, sum0, 2);
        sum1 += __shfl_xor_sync(0xffffffffu, sum1, 1);
        sum1 += __shfl_xor_sync(0xffffffffu, sum1, 2);
        l0 = l0 * al0 + sum0;
        l1 = l1 * al1 + sum1;
        m0 = m0n; m1 = m1n;
        #pragma unroll
        for (int nf = 0; nf < 16; ++nf) {
            o[nf][0] *= al0; o[nf][1] *= al0; o[nf][2] *= al1; o[nf][3] *= al1;
        }

        // ---- O += P V : P accum frag -> fp16 A frag directly in registers ----
        #pragma unroll
        for (int k2 = 0; k2 < 4; ++k2) {
            uint32_t pa[4];
            pa[0] = pack_h2(s[2 * k2][0],     s[2 * k2][1]);
            pa[1] = pack_h2(s[2 * k2][2],     s[2 * k2][3]);
            pa[2] = pack_h2(s[2 * k2 + 1][0], s[2 * k2 + 1][1]);
            pa[3] = pack_h2(s[2 * k2 + 1][2], s[2 * k2 + 1][3]);
            #pragma unroll
            for (int nfp = 0; nfp < 8; ++nfp) {
                uint32_t bv[4];
                ldsm4t(bv, vh_b + (uint32_t)k2 * (16 * ROWB) + nfp * 32);
                mma_f16(o[2 * nfp],     pa, bv);
                mma_f16(o[2 * nfp + 1], pa, bv + 2);
            }
        }
    }

    // ---- epilogue: normalize and store ----
    float inv0 = 1.f / l0, inv1 = 1.f / l1;
    size_t obase = head + (size_t)(q0 + rbase) * DHEAD;
    #pragma unroll
    for (int nf = 0; nf < 16; ++nf) {
        *(float2*)(O + obase + (size_t)(g)     * DHEAD + nf * 8 + c * 2) =
            make_float2(o[nf][0] * inv0, o[nf][1] * inv0);
        *(float2*)(O + obase + (size_t)(g + 8) * DHEAD + nf * 8 + c * 2) =
            make_float2(o[nf][2] * inv1, o[nf][3] * inv1);
    }
}

extern "C" void kernel_launch(void* const* d_in, const int* in_sizes, int n_in,
                              void* d_out, int out_size) {
    const float* q = (const float*)d_in[0];
    const float* k = (const float*)d_in[1];
    const float* v = (const float*)d_in[2];
    float* o = (float*)d_out;

    const size_t smem_bytes = (size_t)(2 * BM * SSTR + 3 * BN * SSTR) * sizeof(__half); // 121856 B

    cudaFuncSetAttribute(fa_f16_kernel, cudaFuncAttributeMaxDynamicSharedMemorySize,
                         (int)smem_bytes);

    dim3 grid(S_LEN / BM, NHEADS);
    fa_f16_kernel<<<grid, THREADS, smem_bytes>>>(q, k, v, o);
}

// round 4
// speedup vs baseline: 2.4773x; 1.3527x over previous
#include <cuda_runtime.h>
#include <cuda_fp16.h>
#include <cstdint>
#include <math.h>

#define S_LEN   2048
#define DHEAD   128
#define NHEADS  64        // B*H = 4*16
#define BM      128
#define BN      32
#define THREADS 256
#define SSTR    136       // fp16 row stride: 272B -> 68 words == 4 mod 32, ldmatrix conflict-free
#define ROWB    272       // SSTR * 2 bytes

// (1/0.32) * log2(e), folded into Q at load
#define SFACT   4.5084219932497354f

static __device__ __forceinline__ float ex2f(float x) {
    float r;
    asm("ex2.approx.f32 %0, %1;" : "=f"(r) : "f"(x));
    return r;
}

static __device__ __forceinline__ uint32_t pack_h2(float a, float b) {
    __half2 h = __floats2half2_rn(a, b);
    return *reinterpret_cast<uint32_t*>(&h);
}

static __device__ __forceinline__ void ldsm4(uint32_t* r, uint32_t a) {
    asm volatile("ldmatrix.sync.aligned.m8n8.x4.shared.b16 {%0,%1,%2,%3}, [%4];"
                 : "=r"(r[0]), "=r"(r[1]), "=r"(r[2]), "=r"(r[3]) : "r"(a));
}

static __device__ __forceinline__ void ldsm4t(uint32_t* r, uint32_t a) {
    asm volatile("ldmatrix.sync.aligned.m8n8.x4.trans.shared.b16 {%0,%1,%2,%3}, [%4];"
                 : "=r"(r[0]), "=r"(r[1]), "=r"(r[2]), "=r"(r[3]) : "r"(a));
}

static __device__ __forceinline__ void mma_f16(float* d, const uint32_t* a, const uint32_t* b) {
    asm volatile(
        "mma.sync.aligned.m16n8k16.row.col.f32.f16.f16.f32 "
        "{%0,%1,%2,%3}, {%4,%5,%6,%7}, {%8,%9}, {%0,%1,%2,%3};\n"
        : "+f"(d[0]), "+f"(d[1]), "+f"(d[2]), "+f"(d[3])
        : "r"(a[0]), "r"(a[1]), "r"(a[2]), "r"(a[3]), "r"(b[0]), "r"(b[1]));
}

// split 8 consecutive floats into hi/lo fp16 planes (packed half2 x4)
static __device__ __forceinline__ void split8(const float* x, uint4& uh, uint4& ul) {
    uint32_t h[4], l[4];
    #pragma unroll
    for (int j = 0; j < 4; ++j) {
        float a = x[2 * j], b = x[2 * j + 1];
        __half ha = __float2half_rn(a), hb = __float2half_rn(b);
        float ra = a - __half2float(ha);
        float rb = b - __half2float(hb);
        h[j] = pack_h2(__half2float(ha), __half2float(hb));
        l[j] = pack_h2(ra, rb);
    }
    uh = make_uint4(h[0], h[1], h[2], h[3]);
    ul = make_uint4(l[0], l[1], l[2], l[3]);
}

static __device__ __forceinline__ uint4 pack8(const float* x) {
    return make_uint4(pack_h2(x[0], x[1]), pack_h2(x[2], x[3]),
                      pack_h2(x[4], x[5]), pack_h2(x[6], x[7]));
}

__global__ __launch_bounds__(THREADS, 2)
void fa_f16_kernel(const float* __restrict__ Q, const float* __restrict__ K,
                   const float* __restrict__ V, float* __restrict__ O) {
    extern __shared__ __align__(16) char smraw[];
    __half* Qh = (__half*)smraw;              // BM * SSTR
    __half* Ql = Qh + BM * SSTR;              // BM * SSTR
    __half* Kh = Ql + BM * SSTR;              // BN * SSTR
    __half* Kl = Kh + BN * SSTR;              // BN * SSTR
    __half* Vh = Kl + BN * SSTR;              // BN * SSTR

    const int tid  = threadIdx.x;
    const int warp = tid >> 5;
    const int lane = tid & 31;
    const int g    = lane >> 2;
    const int c    = lane & 3;

    const int bh = blockIdx.y;
    const int q0 = blockIdx.x * BM;
    const size_t head = (size_t)bh * S_LEN * DHEAD;
    const int rbase = warp * 16;

    // ---- load Q tile: scale, split hi/lo fp16 ----
    for (int i = tid; i < BM * 16; i += THREADS) {
        int row = i >> 4, ch = i & 15;
        const float* src = Q + head + (size_t)(q0 + row) * DHEAD + ch * 8;
        float f[8];
        float4 f0 = *(const float4*)src;
        float4 f1 = *(const float4*)(src + 4);
        f[0] = f0.x * SFACT; f[1] = f0.y * SFACT; f[2] = f0.z * SFACT; f[3] = f0.w * SFACT;
        f[4] = f1.x * SFACT; f[5] = f1.y * SFACT; f[6] = f1.z * SFACT; f[7] = f1.w * SFACT;
        uint4 uh, ul;
        split8(f, uh, ul);
        *(uint4*)(Qh + row * SSTR + ch * 8) = uh;
        *(uint4*)(Ql + row * SSTR + ch * 8) = ul;
    }

    // ---- fragment smem addresses (bytes) ----
    const uint32_t qh_base = (uint32_t)__cvta_generic_to_shared(Qh);
    const uint32_t ql_base = (uint32_t)__cvta_generic_to_shared(Ql);
    const uint32_t kh_base = (uint32_t)__cvta_generic_to_shared(Kh);
    const uint32_t kl_base = (uint32_t)__cvta_generic_to_shared(Kl);
    const uint32_t vh_base = (uint32_t)__cvta_generic_to_shared(Vh);

    // A (Q): rows rbase + (lane&15); k-chunk (lane>>4)
    const uint32_t aoff = (uint32_t)(rbase + (lane & 15)) * ROWB + (lane >> 4) * 16;
    const uint32_t qh_a = qh_base + aoff;
    const uint32_t ql_a = ql_base + aoff;
    // B (K): rows (lane&7) + 8*(lane>>4) [+16*ngp]; k-chunk ((lane>>3)&1)
    const uint32_t boff = (uint32_t)((lane & 7) + ((lane >> 4) << 3)) * ROWB + ((lane >> 3) & 1) * 16;
    const uint32_t kh_b = kh_base + boff;
    const uint32_t kl_b = kl_base + boff;
    // B (V, trans): rows (lane&7) + 8*((lane>>3)&1) [+16*k2]; d-chunk (lane>>4) [+2*nfp]
    const uint32_t voff = (uint32_t)((lane & 7) + (((lane >> 3) & 1) << 3)) * ROWB + (lane >> 4) * 16;
    const uint32_t vh_b = vh_base + voff;

    float o[16][4];
    #pragma unroll
    for (int i = 0; i < 16; i++) { o[i][0] = 0.f; o[i][1] = 0.f; o[i][2] = 0.f; o[i][3] = 0.f; }
    float m0 = -INFINITY, m1 = -INFINITY, l0 = 0.f, l1 = 0.f;

    for (int jt = 0; jt < S_LEN / BN; ++jt) {
        __syncthreads();   // previous tile's smem reads complete (covers Q load at jt=0)
        const int k0 = jt * BN;
        for (int i = tid; i < BN * 16; i += THREADS) {
            int row = i >> 4, ch = i & 15;
            size_t gidx = head + (size_t)(k0 + row) * DHEAD + ch * 8;
            float kf[8], vf[8];
            float4 t0 = *(const float4*)(K + gidx);
            float4 t1 = *(const float4*)(K + gidx + 4);
            kf[0]=t0.x; kf[1]=t0.y; kf[2]=t0.z; kf[3]=t0.w;
            kf[4]=t1.x; kf[5]=t1.y; kf[6]=t1.z; kf[7]=t1.w;
            float4 u0 = *(const float4*)(V + gidx);
            float4 u1 = *(const float4*)(V + gidx + 4);
            vf[0]=u0.x; vf[1]=u0.y; vf[2]=u0.z; vf[3]=u0.w;
            vf[4]=u1.x; vf[5]=u1.y; vf[6]=u1.z; vf[7]=u1.w;
            uint4 uh, ul;
            split8(kf, uh, ul);
            *(uint4*)(Kh + row * SSTR + ch * 8) = uh;
            *(uint4*)(Kl + row * SSTR + ch * 8) = ul;
            *(uint4*)(Vh + row * SSTR + ch * 8) = pack8(vf);
        }
        __syncthreads();

        // ---- S = Q K^T : 3x fp16 split (hh, lh, hl) ----
        float s[4][4];
        #pragma unroll
        for (int i = 0; i < 4; i++) { s[i][0]=0.f; s[i][1]=0.f; s[i][2]=0.f; s[i][3]=0.f; }

        #pragma unroll 2
        for (int kk = 0; kk < 8; ++kk) {
            uint32_t aH[4], aL[4];
            ldsm4(aH, qh_a + kk * 32);
            ldsm4(aL, ql_a + kk * 32);
            uint32_t bhf[8], blf[8];
            #pragma unroll
            for (int ngp = 0; ngp < 2; ++ngp) {
                ldsm4(&bhf[ngp * 4], kh_b + (uint32_t)ngp * (16 * ROWB) + kk * 32);
                ldsm4(&blf[ngp * 4], kl_b + (uint32_t)ngp * (16 * ROWB) + kk * 32);
            }
            #pragma unroll
            for (int ng = 0; ng < 4; ++ng) mma_f16(s[ng], aH, &bhf[ng * 2]);
            #pragma unroll
            for (int ng = 0; ng < 4; ++ng) mma_f16(s[ng], aL, &bhf[ng * 2]);
            #pragma unroll
            for (int ng = 0; ng < 4; ++ng) mma_f16(s[ng], aH, &blf[ng * 2]);
        }

        // ---- online softmax (base-2 domain; scale folded into Q) ----
        float mx0 = -INFINITY, mx1 = -INFINITY;
        #pragma unroll
        for (int ng = 0; ng < 4; ++ng) {
            mx0 = fmaxf(mx0, fmaxf(s[ng][0], s[ng][1]));
            mx1 = fmaxf(mx1, fmaxf(s[ng][2], s[ng][3]));
        }
        mx0 = fmaxf(mx0, __shfl_xor_sync(0xffffffffu, mx0, 1));
        mx0 = fmaxf(mx0, __shfl_xor_sync(0xffffffffu, mx0, 2));
        mx1 = fmaxf(mx1, __shfl_xor_sync(0xffffffffu, mx1, 1));
        mx1 = fmaxf(mx1, __shfl_xor_sync(0xffffffffu, mx1, 2));

        float m0n = fmaxf(m0, mx0), m1n = fmaxf(m1, mx1);
        float al0 = ex2f(m0 - m0n), al1 = ex2f(m1 - m1n);
        float sum0 = 0.f, sum1 = 0.f;
        #pragma unroll
        for (int ng = 0; ng < 4; ++ng) {
            s[ng][0] = ex2f(s[ng][0] - m0n);
            s[ng][1] = ex2f(s[ng][1] - m0n);
            s[ng][2] = ex2f(s[ng][2] - m1n);
            s[ng][3] = ex2f(s[ng][3] - m1n);
            sum0 += s[ng][0] + s[ng][1];
            sum1 += s[ng][2] + s[ng][3];
        }
        sum0 += __shfl_xor_sync(0xffffffffu, sum0, 1);
        sum0 += __shfl_xor_sync(0xffffffffu, sum0, 2);
        sum1 += __shfl_xor_sync(0xffffffffu, sum1, 1);
        sum1 += __shfl_xor_sync(0xffffffffu, sum1, 2);
        l0 = l0 * al0 + sum0;
        l1 = l1 * al1 + sum1;
        m0 = m0n; m1 = m1n;
        #pragma unroll
        for (int nf = 0; nf < 16; ++nf) {
            o[nf][0] *= al0; o[nf][1] *= al0; o[nf][2] *= al1; o[nf][3] *= al1;
        }

        // ---- O += P V : P accum frag -> fp16 A frag directly in registers ----
        #pragma unroll
        for (int k2 = 0; k2 < 2; ++k2) {
            uint32_t pa[4];
            pa[0] = pack_h2(s[2 * k2][0],     s[2 * k2][1]);
            pa[1] = pack_h2(s[2 * k2][2],     s[2 * k2][3]);
            pa[2] = pack_h2(s[2 * k2 + 1][0], s[2 * k2 + 1][1]);
            pa[3] = pack_h2(s[2 * k2 + 1][2], s[2 * k2 + 1][3]);
            #pragma unroll
            for (int nfp = 0; nfp < 8; ++nfp) {
                uint32_t bv[4];
                ldsm4t(bv, vh_b + (uint32_t)k2 * (16 * ROWB) + nfp * 32);
                mma_f16(o[2 * nfp],     pa, bv);
                mma_f16(o[2 * nfp + 1], pa, bv + 2);
            }
        }
    }

    // ---- epilogue: normalize and store ----
    float inv0 = 1.f / l0, inv1 = 1.f / l1;
    size_t obase = head + (size_t)(q0 + rbase) * DHEAD;
    #pragma unroll
    for (int nf = 0; nf < 16; ++nf) {
        *(float2*)(O + obase + (size_t)(g)     * DHEAD + nf * 8 + c * 2) =
            make_float2(o[nf][0] * inv0, o[nf][1] * inv0);
        *(float2*)(O + obase + (size_t)(g + 8) * DHEAD + nf * 8 + c * 2) =
            make_float2(o[nf][2] * inv1, o[nf][3] * inv1);
    }
}

extern "C" void kernel_launch(void* const* d_in, const int* in_sizes, int n_in,
                              void* d_out, int out_size) {
    const float* q = (const float*)d_in[0];
    const float* k = (const float*)d_in[1];
    const float* v = (const float*)d_in[2];
    float* o = (float*)d_out;

    const size_t smem_bytes = (size_t)(2 * BM * SSTR + 3 * BN * SSTR) * sizeof(__half); // 95744 B

    cudaFuncSetAttribute(fa_f16_kernel, cudaFuncAttributeMaxDynamicSharedMemorySize,
                         (int)smem_bytes);

    dim3 grid(S_LEN / BM, NHEADS);
    fa_f16_kernel<<<grid, THREADS, smem_bytes>>>(q, k, v, o);
}

// round 6
// speedup vs baseline: 2.5311x; 1.0217x over previous
#include <cuda_runtime.h>
#include <cuda_fp16.h>
#include <cstdint>
#include <math.h>

#define S_LEN   2048
#define DHEAD   128
#define NHEADS  64        // B*H = 4*16
#define BM      128
#define BN      64
#define THREADS 256

// smem: swizzled 256B rows, no padding
#define SM_QHI  0
#define SM_QLO  32768
#define SM_KHI  65536
#define SM_KLO  81920
#define SM_V    98304
#define SM_TOT  114688

// (1/0.32) * log2(e), folded into Q at load
#define SFACT   4.5084219932497354f

// swizzled byte offset: row (256B each), ch = 16B chunk index 0..15
#define SWZ(row, ch) ((uint32_t)(row) * 256u + (uint32_t)((((ch) ^ ((row) & 7)) << 4)))

static __device__ __forceinline__ float ex2f(float x) {
    float r; asm("ex2.approx.f32 %0, %1;" : "=f"(r) : "f"(x)); return r;
}
static __device__ __forceinline__ uint32_t pack_h2(float a, float b) {
    __half2 h = __floats2half2_rn(a, b);
    return *reinterpret_cast<uint32_t*>(&h);
}
static __device__ __forceinline__ void ldsm4(uint32_t* r, uint32_t a) {
    asm volatile("ldmatrix.sync.aligned.m8n8.x4.shared.b16 {%0,%1,%2,%3}, [%4];"
                 : "=r"(r[0]), "=r"(r[1]), "=r"(r[2]), "=r"(r[3]) : "r"(a));
}
static __device__ __forceinline__ void ldsm4t(uint32_t* r, uint32_t a) {
    asm volatile("ldmatrix.sync.aligned.m8n8.x4.trans.shared.b16 {%0,%1,%2,%3}, [%4];"
                 : "=r"(r[0]), "=r"(r[1]), "=r"(r[2]), "=r"(r[3]) : "r"(a));
}
static __device__ __forceinline__ void mma_f16(float* d, const uint32_t* a, const uint32_t* b) {
    asm volatile(
        "mma.sync.aligned.m16n8k16.row.col.f32.f16.f16.f32 "
        "{%0,%1,%2,%3}, {%4,%5,%6,%7}, {%8,%9}, {%0,%1,%2,%3};\n"
        : "+f"(d[0]), "+f"(d[1]), "+f"(d[2]), "+f"(d[3])
        : "r"(a[0]), "r"(a[1]), "r"(a[2]), "r"(a[3]), "r"(b[0]), "r"(b[1]));
}
// split 8 consecutive floats into hi/lo fp16 planes (packed half2 x4)
static __device__ __forceinline__ void split8(const float* x, uint4& uh, uint4& ul) {
    uint32_t h[4], l[4];
    #pragma unroll
    for (int j = 0; j < 4; ++j) {
        float a = x[2 * j], b = x[2 * j + 1];
        __half ha = __float2half_rn(a), hb = __float2half_rn(b);
        h[j] = pack_h2(__half2float(ha), __half2float(hb));
        l[j] = pack_h2(a - __half2float(ha), b - __half2float(hb));
    }
    uh = make_uint4(h[0], h[1], h[2], h[3]);
    ul = make_uint4(l[0], l[1], l[2], l[3]);
}
static __device__ __forceinline__ uint4 pack8(const float* x) {
    return make_uint4(pack_h2(x[0], x[1]), pack_h2(x[2], x[3]),
                      pack_h2(x[4], x[5]), pack_h2(x[6], x[7]));
}

__global__ __launch_bounds__(THREADS, 2)
void fa_swz_kernel(const float* __restrict__ Q, const float* __restrict__ K,
                   const float* __restrict__ V, float* __restrict__ O) {
    extern __shared__ __align__(16) char sm[];
    const uint32_t smb = (uint32_t)__cvta_generic_to_shared(sm);

    const int tid  = threadIdx.x;
    const int warp = tid >> 5;
    const int lane = tid & 31;
    const int g    = lane >> 2;
    const int c    = lane & 3;
    const uint32_t rl = lane & 7;   // swizzle row-low bits (invariant for all frag rows)

    const int bh = blockIdx.y;
    const int q0 = blockIdx.x * BM;
    const size_t head = (size_t)bh * S_LEN * DHEAD;
    const int rbase = warp * 16;

    // ---- load Q tile: scale, split hi/lo fp16, swizzled store ----
    for (int i = tid; i < BM * 16; i += THREADS) {
        int row = i >> 4, ch = i & 15;
        const float* src = Q + head + (size_t)(q0 + row) * DHEAD + ch * 8;
        float4 f0 = *(const float4*)src;
        float4 f1 = *(const float4*)(src + 4);
        float f[8] = {f0.x*SFACT, f0.y*SFACT, f0.z*SFACT, f0.w*SFACT,
                      f1.x*SFACT, f1.y*SFACT, f1.z*SFACT, f1.w*SFACT};
        uint4 uh, ul; split8(f, uh, ul);
        uint32_t off = SWZ(row, ch);
        *(uint4*)(sm + SM_QHI + off) = uh;
        *(uint4*)(sm + SM_QLO + off) = ul;
    }

    // ---- per-lane fragment base addresses (row parts; chunk XOR applied per use) ----
    // A (Q): row = rbase + (lane&15); chunk0 = lane>>4
    const uint32_t qrow = (uint32_t)(rbase + (lane & 15)) * 256u;
    const uint32_t qA_h = smb + SM_QHI + qrow;
    const uint32_t qA_l = smb + SM_QLO + qrow;
    const uint32_t chA0 = lane >> 4;
    // B (K): row = (lane&7) + 8*(lane>>4) [+16*ngp]; chunk0 = (lane>>3)&1
    const uint32_t krow = (uint32_t)((lane & 7) + ((lane >> 4) << 3)) * 256u;
    const uint32_t kB_h = smb + SM_KHI + krow;
    const uint32_t kB_l = smb + SM_KLO + krow;
    const uint32_t chB0 = (lane >> 3) & 1;
    // B (V, trans): row = (lane&7) + 8*((lane>>3)&1) [+16*k2]; chunk0 = lane>>4
    const uint32_t vrow = (uint32_t)((lane & 7) + (((lane >> 3) & 1) << 3)) * 256u;
    const uint32_t vB   = smb + SM_V + vrow;
    const uint32_t chV0 = lane >> 4;

    float o[16][4];
    #pragma unroll
    for (int i = 0; i < 16; i++) { o[i][0]=0.f; o[i][1]=0.f; o[i][2]=0.f; o[i][3]=0.f; }
    float m0 = -INFINITY, m1 = -INFINITY, l0 = 0.f, l1 = 0.f;

    for (int jt = 0; jt < S_LEN / BN; ++jt) {
        __syncthreads();   // previous tile's smem reads complete (covers Q load at jt=0)
        const int k0 = jt * BN;
        for (int i = tid; i < BN * 16; i += THREADS) {
            int row = i >> 4, ch = i & 15;
            size_t gidx = head + (size_t)(k0 + row) * DHEAD + ch * 8;
            float4 t0 = *(const float4*)(K + gidx);
            float4 t1 = *(const float4*)(K + gidx + 4);
            float kf[8] = {t0.x,t0.y,t0.z,t0.w,t1.x,t1.y,t1.z,t1.w};
            uint4 uh, ul; split8(kf, uh, ul);
            uint32_t off = SWZ(row, ch);
            *(uint4*)(sm + SM_KHI + off) = uh;
            *(uint4*)(sm + SM_KLO + off) = ul;
            float4 u0 = *(const float4*)(V + gidx);
            float4 u1 = *(const float4*)(V + gidx + 4);
            float vf[8] = {u0.x,u0.y,u0.z,u0.w,u1.x,u1.y,u1.z,u1.w};
            *(uint4*)(sm + SM_V + off) = pack8(vf);
        }
        __syncthreads();

        // ---- S = Q K^T : 3x fp16 split (hh, lh, hl) ----
        float s[8][4];
        #pragma unroll
        for (int i = 0; i < 8; i++) { s[i][0]=0.f; s[i][1]=0.f; s[i][2]=0.f; s[i][3]=0.f; }

        #pragma unroll 2
        for (int kk = 0; kk < 8; ++kk) {
            const uint32_t offA = ((chA0 + 2 * kk) ^ rl) << 4;
            uint32_t aH[4], aL[4];
            ldsm4(aH, qA_h + offA);
            ldsm4(aL, qA_l + offA);
            const uint32_t offB = ((chB0 + 2 * kk) ^ rl) << 4;
            #pragma unroll
            for (int hfl = 0; hfl < 2; ++hfl) {   // two halves of BN: ng 0..3 / 4..7
                const uint32_t bbase = (uint32_t)hfl * 8192u + offB;
                uint32_t bhf[8], blf[8];
                ldsm4(&bhf[0], kB_h + bbase);
                ldsm4(&bhf[4], kB_h + bbase + 4096u);
                ldsm4(&blf[0], kB_l + bbase);
                ldsm4(&blf[4], kB_l + bbase + 4096u);
                float (*sp)[4] = &s[hfl * 4];
                #pragma unroll
                for (int j = 0; j < 4; ++j) mma_f16(sp[j], aH, &bhf[j * 2]);
                #pragma unroll
                for (int j = 0; j < 4; ++j) mma_f16(sp[j], aL, &bhf[j * 2]);
                #pragma unroll
                for (int j = 0; j < 4; ++j) mma_f16(sp[j], aH, &blf[j * 2]);
            }
        }

        // ---- online softmax (base-2 domain; scale folded into Q) ----
        float mx0 = -INFINITY, mx1 = -INFINITY;
        #pragma unroll
        for (int ng = 0; ng < 8; ++ng) {
            mx0 = fmaxf(mx0, fmaxf(s[ng][0], s[ng][1]));
            mx1 = fmaxf(mx1, fmaxf(s[ng][2], s[ng][3]));
        }
        mx0 = fmaxf(mx0, __shfl_xor_sync(0xffffffffu, mx0, 1));
        mx0 = fmaxf(mx0, __shfl_xor_sync(0xffffffffu, mx0, 2));
        mx1 = fmaxf(mx1, __shfl_xor_sync(0xffffffffu, mx1, 1));
        mx1 = fmaxf(mx1, __shfl_xor_sync(0xffffffffu, mx1, 2));

        float m0n = fmaxf(m0, mx0), m1n = fmaxf(m1, mx1);
        float al0 = ex2f(m0 - m0n), al1 = ex2f(m1 - m1n);
        float sum0 = 0.f, sum1 = 0.f;
        #pragma unroll
        for (int ng = 0; ng < 8; ++ng) {
            s[ng][0] = ex2f(s[ng][0] - m0n);
            s[ng][1] = ex2f(s[ng][1] - m0n);
            s[ng][2] = ex2f(s[ng][2] - m1n);
            s[ng][3] = ex2f(s[ng][3] - m1n);
            sum0 += s[ng][0] + s[ng][1];
            sum1 += s[ng][2] + s[ng][3];
        }
        sum0 += __shfl_xor_sync(0xffffffffu, sum0, 1);
        sum0 += __shfl_xor_sync(0xffffffffu, sum0, 2);
        sum1 += __shfl_xor_sync(0xffffffffu, sum1, 1);
        sum1 += __shfl_xor_sync(0xffffffffu, sum1, 2);
        l0 = l0 * al0 + sum0;
        l1 = l1 * al1 + sum1;
        m0 = m0n; m1 = m1n;
        #pragma unroll
        for (int nf = 0; nf < 16; ++nf) {
            o[nf][0] *= al0; o[nf][1] *= al0; o[nf][2] *= al1; o[nf][3] *= al1;
        }

        // ---- O += P V : P accum frag -> fp16 A frag directly in registers ----
        #pragma unroll
        for (int k2 = 0; k2 < 4; ++k2) {
            uint32_t pa[4];
            pa[0] = pack_h2(s[2 * k2][0],     s[2 * k2][1]);
            pa[1] = pack_h2(s[2 * k2][2],     s[2 * k2][3]);
            pa[2] = pack_h2(s[2 * k2 + 1][0], s[2 * k2 + 1][1]);
            pa[3] = pack_h2(s[2 * k2 + 1][2], s[2 * k2 + 1][3]);
            #pragma unroll
            for (int nfp = 0; nfp < 8; ++nfp) {
                const uint32_t offV = ((chV0 + 2 * nfp) ^ rl) << 4;
                uint32_t bv[4];
                ldsm4t(bv, vB + (uint32_t)k2 * 4096u + offV);
                mma_f16(o[2 * nfp],     pa, bv);
                mma_f16(o[2 * nfp + 1], pa, bv + 2);
            }
        }
    }

    // ---- epilogue: normalize and store ----
    float inv0 = 1.f / l0, inv1 = 1.f / l1;
    size_t obase = head + (size_t)(q0 + rbase) * DHEAD;
    #pragma unroll
    for (int nf = 0; nf < 16; ++nf) {
        *(float2*)(O + obase + (size_t)(g)     * DHEAD + nf * 8 + c * 2) =
            make_float2(o[nf][0] * inv0, o[nf][1] * inv0);
        *(float2*)(O + obase + (size_t)(g + 8) * DHEAD + nf * 8 + c * 2) =
            make_float2(o[nf][2] * inv1, o[nf][3] * inv1);
    }
}

extern "C" void kernel_launch(void* const* d_in, const int* in_sizes, int n_in,
                              void* d_out, int out_size) {
    const float* q = (const float*)d_in[0];
    const float* k = (const float*)d_in[1];
    const float* v = (const float*)d_in[2];
    float* o = (float*)d_out;

    cudaFuncSetAttribute(fa_swz_kernel, cudaFuncAttributeMaxDynamicSharedMemorySize, SM_TOT);

    dim3 grid(S_LEN / BM, NHEADS);
    fa_swz_kernel<<<grid, THREADS, SM_TOT>>>(q, k, v, o);
}